// round 7
// baseline (speedup 1.0000x reference)
#include <cuda_runtime.h>
#include <cuda_bf16.h>
#include <cstdint>

// ---------------------------------------------------------------------------
// Spiking Swin block:
//   q,k,v = lif(x @ W^T)  -> binary, bitpacked (literal reshape == flat bitpack)
//   attn  = SCALE*popc(q&k) + rpb          (written to d_out[8388608..])
//   out1  = attn @ v  (v binary; zero v-tile -> flag, no traffic)
//   out   = lif(out1 @ Wproj^T + bproj)    (written to d_out[0..8388608))
// ---------------------------------------------------------------------------

#define TOK_TOTAL 16384          // B_*H*W = 256*64
#define SCALE_F   0.17677669529663687f

__device__ unsigned g_qbits[262144];
__device__ unsigned g_kbits[262144];
__device__ unsigned g_vbits[262144];
__device__ int      g_vnz[1024];       // per (b',head): v tile has any spike
__device__ float    g_out1[8388608];   // proj input; only written where flag!=0

// ------------------------------- Stage A -----------------------------------
// Fused q/k/v: block loads its x tile ONCE (fp32 -> bf16 in-flight), then for
// each of Wq/Wk/Wv: load W -> MMA -> LIF+bitpack. Epilogue staging buffer
// aliases the W buffer (A tile survives), processed in two 64-channel halves
// so total smem = 69.6KB -> 2 CTAs/SM at 512 threads.
#define PA  136   // bf16 pitch (272B: conflict-free fragment loads)
#define PYH 68    // fp32 pitch for half-width epilogue staging

__global__ void __launch_bounds__(512, 2) gemm_qkv_lif_kernel(
    const float* __restrict__ x,
    const float* __restrict__ Wq,
    const float* __restrict__ Wk,
    const float* __restrict__ Wv)
{
    extern __shared__ char smem_raw[];
    __nv_bfloat16* Ah = (__nv_bfloat16*)smem_raw;                // 34816 B
    __nv_bfloat16* Bh = Ah + 128 * PA;                           // 34816 B
    float* Ysm = (float*)(smem_raw + 128 * PA * 2);              // aliases Bh

    const int tid = threadIdx.x;
    const int tokbase = blockIdx.x * 32;

    // ---- load X tile (4t x 32tok x 128ch) once, fp32 -> bf16
#pragma unroll
    for (int it = 0; it < 2; ++it) {
        int idx = it * 512 + tid;              // float4 id, 1024 total
        int m = idx >> 3, c4 = idx & 7;        // smem row m = t*32+i
        int t = m >> 5, i = m & 31;
        float4 v4 = *(const float4*)(x + (size_t)(t * TOK_TOTAL + tokbase + i) * 128 + c4 * 4);
        __nv_bfloat162* d = (__nv_bfloat162*)(Ah + m * PA + c4 * 4);
        d[0] = __floats2bfloat162_rn(v4.x, v4.y);
        d[1] = __floats2bfloat162_rn(v4.z, v4.w);
    }

    const int w = tid >> 5, lane = tid & 31;
    const int wm = w & 3, wn = w >> 2;         // warp tile: 32 rows x 32 cols
    const int g = lane >> 2, tq = lane & 3;

#pragma unroll 1
    for (int nb = 0; nb < 3; ++nb) {
        const float* W = (nb == 0) ? Wq : ((nb == 1) ? Wk : Wv);
        __syncthreads();   // A ready (nb=0); prev LIF reads of Ysm done (nb>0)

        // ---- load W (fp32 -> bf16) into Bh
#pragma unroll
        for (int it = 0; it < 2; ++it) {
            int idx = it * 512 + tid;
            int m = idx >> 3, c4 = idx & 7;
            float4 v4 = *(const float4*)(W + (size_t)m * 128 + c4 * 4);
            __nv_bfloat162* d = (__nv_bfloat162*)(Bh + m * PA + c4 * 4);
            d[0] = __floats2bfloat162_rn(v4.x, v4.y);
            d[1] = __floats2bfloat162_rn(v4.z, v4.w);
        }
        __syncthreads();

        float c[2][4][4];
#pragma unroll
        for (int mt = 0; mt < 2; ++mt)
#pragma unroll
            for (int nt = 0; nt < 4; ++nt)
#pragma unroll
                for (int r = 0; r < 4; ++r) c[mt][nt][r] = 0.f;

#pragma unroll
        for (int kk = 0; kk < 8; ++kk) {
            const int kc = kk * 16 + tq * 2;
            unsigned b0[4], b1[4];
#pragma unroll
            for (int nt = 0; nt < 4; ++nt) {
                const __nv_bfloat16* bp = Bh + (wn * 32 + nt * 8 + g) * PA + kc;
                b0[nt] = *(const unsigned*)bp;
                b1[nt] = *(const unsigned*)(bp + 8);
            }
#pragma unroll
            for (int mt = 0; mt < 2; ++mt) {
                const __nv_bfloat16* ap = Ah + (wm * 32 + mt * 16 + g) * PA + kc;
                unsigned a0 = *(const unsigned*)ap;
                unsigned a1 = *(const unsigned*)(ap + 8 * PA);
                unsigned a2 = *(const unsigned*)(ap + 8);
                unsigned a3 = *(const unsigned*)(ap + 8 * PA + 8);
#pragma unroll
                for (int nt = 0; nt < 4; ++nt) {
                    asm volatile(
                        "mma.sync.aligned.m16n8k16.row.col.f32.bf16.bf16.f32 "
                        "{%0,%1,%2,%3}, {%4,%5,%6,%7}, {%8,%9}, {%0,%1,%2,%3};"
                        : "+f"(c[mt][nt][0]), "+f"(c[mt][nt][1]),
                          "+f"(c[mt][nt][2]), "+f"(c[mt][nt][3])
                        : "r"(a0), "r"(a1), "r"(a2), "r"(a3),
                          "r"(b0[nt]), "r"(b1[nt]));
                }
            }
        }
        __syncthreads();   // all MMA reads of Bh done; Ysm may clobber it

        unsigned* dst = (nb == 0) ? g_qbits : ((nb == 1) ? g_kbits : g_vbits);
#pragma unroll 1
        for (int h = 0; h < 2; ++h) {
            // stage accumulators for channel half h (warps wn in {2h, 2h+1})
            if ((wn >> 1) == h) {
#pragma unroll
                for (int mt = 0; mt < 2; ++mt)
#pragma unroll
                    for (int nt = 0; nt < 4; ++nt) {
                        int r0 = wm * 32 + mt * 16 + g;
                        int cc = (wn & 1) * 32 + nt * 8 + tq * 2;
                        Ysm[r0 * PYH + cc]           = c[mt][nt][0];
                        Ysm[r0 * PYH + cc + 1]       = c[mt][nt][1];
                        Ysm[(r0 + 8) * PYH + cc]     = c[mt][nt][2];
                        Ysm[(r0 + 8) * PYH + cc + 1] = c[mt][nt][3];
                    }
            }
            __syncthreads();

            // LIF over t + bitpack for this half: token i = tid>>4, 4 chans
            const int i = tid >> 4;
            const int cq = tid & 15;           // local chans cq*4..+3
            float4 y0 = *(const float4*)&Ysm[(0 * 32 + i) * PYH + cq * 4];
            float4 y1 = *(const float4*)&Ysm[(1 * 32 + i) * PYH + cq * 4];
            float4 y2 = *(const float4*)&Ysm[(2 * 32 + i) * PYH + cq * 4];
            float4 y3 = *(const float4*)&Ysm[(3 * 32 + i) * PYH + cq * 4];
            float ya[4][4] = {{y0.x, y0.y, y0.z, y0.w},
                              {y1.x, y1.y, y1.z, y1.w},
                              {y2.x, y2.y, y2.z, y2.w},
                              {y3.x, y3.y, y3.z, y3.w}};
            unsigned nib[4] = {0u, 0u, 0u, 0u};
#pragma unroll
            for (int j = 0; j < 4; ++j) {
                float v = 0.f;
#pragma unroll
                for (int t = 0; t < 4; ++t) {
                    v += (ya[t][j] - v) * 0.5f;    // v + (x - v)/tau, tau=2
                    if (v >= 1.0f) { nib[t] |= (1u << j); v = 0.f; }
                }
            }
            const unsigned sh = (cq & 7) * 4;
#pragma unroll
            for (int t = 0; t < 4; ++t) {
                unsigned b = nib[t] << sh;
                b |= __shfl_xor_sync(0xffffffffu, b, 1);
                b |= __shfl_xor_sync(0xffffffffu, b, 2);
                b |= __shfl_xor_sync(0xffffffffu, b, 4);
                if ((cq & 7) == 0)
                    dst[(t * TOK_TOTAL + tokbase + i) * 4 + h * 2 + (cq >> 3)] = b;
            }
            __syncthreads();   // LIF reads done before next stage/nb clobbers
        }
    }
}

// ------------------------------- Stage B -----------------------------------
// One block per (b', head): attn = SCALE*popc(q&k)+rpb -> d_out (float4,
// streaming stores). out1 = attn@v only if v has spikes. If ALL 4 heads of
// this b' are spike-free, the final output equals lif(bproj) broadcast --
// this block writes its own 32-channel slice of that inline.
__global__ void __launch_bounds__(256) attn_kernel(
    const float* __restrict__ rpb_table, const float* __restrict__ bproj,
    float* __restrict__ out)
{
    __shared__ unsigned qw[256], kw[256], vw[256];
    __shared__ float rpb_sm[1575];             // per-head slice, stride-1

    const int tid = threadIdx.x;
    const int bh = blockIdx.x;                 // = b'*4 + head
    const int bq = bh >> 2, head = bh & 3;

    qw[tid] = g_qbits[bh * 256 + tid];
    kw[tid] = g_kbits[bh * 256 + tid];
    vw[tid] = g_vbits[bh * 256 + tid];
    unsigned vall = g_vbits[(bq * 4 + 0) * 256 + tid] |
                    g_vbits[(bq * 4 + 1) * 256 + tid] |
                    g_vbits[(bq * 4 + 2) * 256 + tid] |
                    g_vbits[(bq * 4 + 3) * 256 + tid];
    for (int idx = tid; idx < 1575; idx += 256)
        rpb_sm[idx] = rpb_table[idx * 4 + head];
    __syncthreads();

    // thread owns 4 consecutive m columns; 4 n-rows in flight per iteration
    const int u = tid & 63;                    // m-quad
    const int grp = tid >> 6;                  // n offset within group of 4
    unsigned km[4];
    int zm[4], ym[4], xm[4];
#pragma unroll
    for (int j = 0; j < 4; ++j) {
        int m = u * 4 + j;
        km[j] = kw[m];
        zm[j] = m >> 6; ym[j] = (m >> 3) & 7; xm[j] = m & 7;
    }
    float4* aout = (float4*)(out + 8388608 + (size_t)bh * 65536);
#pragma unroll 2
    for (int nb = 0; nb < 256; nb += 4) {
        int n = nb + grp;
        int zn = n >> 6, yn = (n >> 3) & 7, xn = n & 7;
        unsigned qn = qw[n];
        float4 r;
        {
            int ridx = (zn - zm[0] + 3) * 225 + (yn - ym[0] + 7) * 15 + (xn - xm[0] + 7);
            r.x = SCALE_F * (float)__popc(qn & km[0]) + rpb_sm[ridx];
        }
        {
            int ridx = (zn - zm[1] + 3) * 225 + (yn - ym[1] + 7) * 15 + (xn - xm[1] + 7);
            r.y = SCALE_F * (float)__popc(qn & km[1]) + rpb_sm[ridx];
        }
        {
            int ridx = (zn - zm[2] + 3) * 225 + (yn - ym[2] + 7) * 15 + (xn - xm[2] + 7);
            r.z = SCALE_F * (float)__popc(qn & km[2]) + rpb_sm[ridx];
        }
        {
            int ridx = (zn - zm[3] + 3) * 225 + (yn - ym[3] + 7) * 15 + (xn - xm[3] + 7);
            r.w = SCALE_F * (float)__popc(qn & km[3]) + rpb_sm[ridx];
        }
        __stcs(&aout[(size_t)n * 64 + u], r);
    }

    // flags
    int vnz  = __syncthreads_or(vw[tid] != 0u);
    int anyv = __syncthreads_or(vall != 0u);
    if (tid == 0) g_vnz[bh] = vnz;

    if (!anyv) {
        // whole b' spike-free: out == lif(bproj) broadcast; write our
        // 32-channel slice for all 64 tokens x 4 timesteps.
        const int hw = tid >> 2, fq = tid & 3;
        float4* o4 = (float4*)out;
#pragma unroll
        for (int ff = 0; ff < 2; ++ff) {
            int f4 = fq + ff * 4;              // float4 index within head slice
            float4 b4 = *(const float4*)(bproj + head * 32 + f4 * 4);
            float4 v = make_float4(0.f, 0.f, 0.f, 0.f);
#pragma unroll
            for (int t = 0; t < 4; ++t) {
                v.x += (b4.x - v.x) * 0.5f; v.y += (b4.y - v.y) * 0.5f;
                v.z += (b4.z - v.z) * 0.5f; v.w += (b4.w - v.w) * 0.5f;
                float4 s;
                s.x = (v.x >= 1.f) ? 1.f : 0.f; if (v.x >= 1.f) v.x = 0.f;
                s.y = (v.y >= 1.f) ? 1.f : 0.f; if (v.y >= 1.f) v.y = 0.f;
                s.z = (v.z >= 1.f) ? 1.f : 0.f; if (v.z >= 1.f) v.z = 0.f;
                s.w = (v.w >= 1.f) ? 1.f : 0.f; if (v.w >= 1.f) v.w = 0.f;
                __stcs(&o4[(size_t)(t * TOK_TOTAL + bq * 64 + hw) * 32 + head * 8 + f4], s);
            }
        }
        return;
    }

    if (vnz) {
        __shared__ int mlist[256];
        __shared__ int mcount;
        if (tid == 0) mcount = 0;
        __syncthreads();
        if (vw[tid] != 0u) { int p = atomicAdd(&mcount, 1); mlist[p] = tid; }
        __syncthreads();
        int cnt = mcount;
        for (int p = tid; p < 8192; p += 256) {
            int n = p >> 5, hd = p & 31;
            int zn = n >> 6, yn = (n >> 3) & 7, xn = n & 7;
            unsigned qn = qw[n];
            float acc = 0.f;
            for (int j = 0; j < cnt; ++j) {
                int m = mlist[j];
                if ((vw[m] >> hd) & 1u) {
                    int zk = m >> 6, yk = (m >> 3) & 7, xk = m & 7;
                    int ridx = (zn - zk + 3) * 225 + (yn - yk + 7) * 15 + (xn - xk + 7);
                    acc += SCALE_F * (float)__popc(qn & kw[m]) + rpb_sm[ridx];
                }
            }
            int row2 = (n >> 6) * TOK_TOTAL + bq * 64 + (n & 63);
            g_out1[(size_t)row2 * 128 + head * 32 + hd] = acc;
        }
    }
}

// ------------------------------- Stage C -----------------------------------
// Fallback only: any head of this b' has v spikes -> full GEMM + LIF.
// (All-zero b' was already written inline by attn_kernel.)
#define PX 132
__global__ void __launch_bounds__(256) proj_lif_kernel(
    const float* __restrict__ Wproj, const float* __restrict__ bproj,
    float* __restrict__ dout)
{
    extern __shared__ float sm[];
    float* X2s = sm;                 // 128 x PX
    float* Wsm = sm + 128 * PX;      // 128 x 128, stored transposed [k][d]
    __shared__ int hflag[4];

    const int tid = threadIdx.x;
    const int tokbase = blockIdx.x * 32;
    const int bq = tokbase >> 6;     // 32 tokens always inside one b'

    if (tid < 4) hflag[tid] = g_vnz[bq * 4 + tid];
    __syncthreads();
    if (!(hflag[0] | hflag[1] | hflag[2] | hflag[3])) return;  // attn wrote it

    {
        const int lane = tid & 31, rg = tid >> 5;
        const int hfl = hflag[lane >> 3];      // float4 spans one head's chans
        for (int it = 0; it < 16; ++it) {
            int m = it * 8 + rg;
            int t = m >> 5, i = m & 31;
            float4 v4 = hfl
                ? *(const float4*)(g_out1 + (size_t)(t * TOK_TOTAL + tokbase + i) * 128 + lane * 4)
                : make_float4(0.f, 0.f, 0.f, 0.f);
            X2s[m * PX + lane * 4 + 0] = v4.x;
            X2s[m * PX + lane * 4 + 1] = v4.y;
            X2s[m * PX + lane * 4 + 2] = v4.z;
            X2s[m * PX + lane * 4 + 3] = v4.w;
        }
    }
    for (int idx = tid; idx < 16384; idx += 256) {
        int d = idx >> 7, k = idx & 127;
        Wsm[k * 128 + d] = Wproj[idx];         // transpose: conflict-free reads
    }
    __syncthreads();
    const int d = tid & 127, i0 = tid >> 7;
    float bj = bproj[d];
    for (int jj = 0; jj < 16; ++jj) {
        int i = i0 * 16 + jj;
        float a0 = 0.f, a1 = 0.f, a2 = 0.f, a3 = 0.f;
        for (int k = 0; k < 128; ++k) {
            float wv = Wsm[k * 128 + d];
            a0 += X2s[(0 * 32 + i) * PX + k] * wv;
            a1 += X2s[(1 * 32 + i) * PX + k] * wv;
            a2 += X2s[(2 * 32 + i) * PX + k] * wv;
            a3 += X2s[(3 * 32 + i) * PX + k] * wv;
        }
        float ys[4] = {a0 + bj, a1 + bj, a2 + bj, a3 + bj};
        float v = 0.f;
#pragma unroll
        for (int t = 0; t < 4; ++t) {
            v += (ys[t] - v) * 0.5f;
            float s = (v >= 1.f) ? 1.f : 0.f;
            if (v >= 1.f) v = 0.f;
            dout[(size_t)(t * TOK_TOTAL + tokbase + i) * 128 + d] = s;
        }
    }
}

// ---------------------------------------------------------------------------
extern "C" void kernel_launch(void* const* d_in, const int* in_sizes, int n_in,
                              void* d_out, int out_size) {
    const float* x   = (const float*)d_in[0];
    const float* Wq  = (const float*)d_in[1];
    const float* Wk  = (const float*)d_in[2];
    const float* Wv  = (const float*)d_in[3];
    const float* rpb = (const float*)d_in[4];
    const float* Wp  = (const float*)d_in[5];
    const float* bp  = (const float*)d_in[6];
    float* out = (float*)d_out;

    const int gemm_smem = 2 * 128 * PA * 2;            // 69632 B -> 2 CTAs/SM
    const int proj_smem = (128 * PX + 16384) * 4;      // 133120 B
    cudaFuncSetAttribute(gemm_qkv_lif_kernel,
                         cudaFuncAttributeMaxDynamicSharedMemorySize, gemm_smem);
    cudaFuncSetAttribute(proj_lif_kernel,
                         cudaFuncAttributeMaxDynamicSharedMemorySize, proj_smem);

    gemm_qkv_lif_kernel<<<512, 512, gemm_smem>>>(x, Wq, Wk, Wv);
    attn_kernel<<<1024, 256>>>(rpb, bp, out);
    proj_lif_kernel<<<512, 256, proj_smem>>>(Wp, bp, out);
}

// round 9
// speedup vs baseline: 1.2433x; 1.2433x over previous
#include <cuda_runtime.h>
#include <cuda_bf16.h>
#include <cstdint>

// ---------------------------------------------------------------------------
// Spiking Swin block:
//   q,k,v = lif(x @ W^T)  -> binary, bitpacked (literal reshape == flat bitpack)
//   attn  = SCALE*popc(q&k) + rpb          (written to d_out[8388608..])
//   out1  = attn @ v  (v binary; zero v-tile -> flag, no traffic)
//   out   = lif(out1 @ Wproj^T + bproj)    (written to d_out[0..8388608))
// ---------------------------------------------------------------------------

#define TOK_TOTAL 16384          // B_*H*W = 256*64
#define SCALE_F   0.17677669529663687f

__device__ unsigned g_qbits[262144];
__device__ unsigned g_kbits[262144];
__device__ unsigned g_vbits[262144];
__device__ int      g_vnz[1024];       // per (b',head): v tile has any spike
__device__ float    g_out1[8388608];   // proj input; only written where flag!=0

// ------------------------------- Stage A -----------------------------------
// C(128x128) = X_tile(128x128) @ W^T in bf16 (abs err ~4e-4 vs fp32; LIF
// margin to threshold is >0.25, so spike bits are exact), then LIF over the
// 4 time rows and bitpack spikes. One block per (32-token tile, q/k/v).
// 512 threads, warp tile 32x32 -> 2 CTAs/SM. fp32 -> bf16 converted in-flight.
#define PA 136   // bf16 pitch (272B: conflict-free fragment loads)
#define PY 132   // fp32 pitch for epilogue staging

__global__ void __launch_bounds__(512, 2) gemm_qkv_lif_kernel(
    const float* __restrict__ x,
    const float* __restrict__ Wq,
    const float* __restrict__ Wk,
    const float* __restrict__ Wv)
{
    extern __shared__ char smem_raw[];
    __nv_bfloat16* Ah = (__nv_bfloat16*)smem_raw;      // 34816 B
    __nv_bfloat16* Bh = Ah + 128 * PA;                 // 34816 B
    float* Ysm = (float*)smem_raw;                     // aliases A+B after MMA

    const int tid = threadIdx.x;
    const int nb = blockIdx.y;                 // 0:q 1:k 2:v
    const int tokbase = blockIdx.x * 32;
    const float* W = (nb == 0) ? Wq : ((nb == 1) ? Wk : Wv);

    // ---- load X tile (4t x 32tok x 128ch) + W (128x128), fp32 -> bf16.
    // 128 rows x 32 float4/row = 4096 float4 per matrix: 8 iters x 512 thr.
#pragma unroll
    for (int it = 0; it < 8; ++it) {
        int idx = it * 512 + tid;              // float4 id, 4096 total
        int m = idx >> 5, c4 = idx & 31;       // smem row m = t*32+i
        int t = m >> 5, i = m & 31;
        float4 v4 = *(const float4*)(x + (size_t)(t * TOK_TOTAL + tokbase + i) * 128 + c4 * 4);
        __nv_bfloat162* d = (__nv_bfloat162*)(Ah + m * PA + c4 * 4);
        d[0] = __floats2bfloat162_rn(v4.x, v4.y);
        d[1] = __floats2bfloat162_rn(v4.z, v4.w);
        float4 w4 = *(const float4*)(W + (size_t)m * 128 + c4 * 4);
        __nv_bfloat162* dw = (__nv_bfloat162*)(Bh + m * PA + c4 * 4);
        dw[0] = __floats2bfloat162_rn(w4.x, w4.y);
        dw[1] = __floats2bfloat162_rn(w4.z, w4.w);
    }
    __syncthreads();

    const int w = tid >> 5, lane = tid & 31;
    const int wm = w & 3, wn = w >> 2;         // warp tile: 32 rows x 32 cols
    const int g = lane >> 2, tq = lane & 3;

    float c[2][4][4];
#pragma unroll
    for (int mt = 0; mt < 2; ++mt)
#pragma unroll
        for (int nt = 0; nt < 4; ++nt)
#pragma unroll
            for (int r = 0; r < 4; ++r) c[mt][nt][r] = 0.f;

#pragma unroll
    for (int kk = 0; kk < 8; ++kk) {
        const int kc = kk * 16 + tq * 2;
        unsigned b0[4], b1[4];
#pragma unroll
        for (int nt = 0; nt < 4; ++nt) {
            const __nv_bfloat16* bp = Bh + (wn * 32 + nt * 8 + g) * PA + kc;
            b0[nt] = *(const unsigned*)bp;
            b1[nt] = *(const unsigned*)(bp + 8);
        }
#pragma unroll
        for (int mt = 0; mt < 2; ++mt) {
            const __nv_bfloat16* ap = Ah + (wm * 32 + mt * 16 + g) * PA + kc;
            unsigned a0 = *(const unsigned*)ap;
            unsigned a1 = *(const unsigned*)(ap + 8 * PA);
            unsigned a2 = *(const unsigned*)(ap + 8);
            unsigned a3 = *(const unsigned*)(ap + 8 * PA + 8);
#pragma unroll
            for (int nt = 0; nt < 4; ++nt) {
                asm volatile(
                    "mma.sync.aligned.m16n8k16.row.col.f32.bf16.bf16.f32 "
                    "{%0,%1,%2,%3}, {%4,%5,%6,%7}, {%8,%9}, {%0,%1,%2,%3};"
                    : "+f"(c[mt][nt][0]), "+f"(c[mt][nt][1]),
                      "+f"(c[mt][nt][2]), "+f"(c[mt][nt][3])
                    : "r"(a0), "r"(a1), "r"(a2), "r"(a3),
                      "r"(b0[nt]), "r"(b1[nt]));
            }
        }
    }
    __syncthreads();   // Ysm aliases A/B tiles — all MMA reads must be done

    // ---- stage accumulators to smem
#pragma unroll
    for (int mt = 0; mt < 2; ++mt)
#pragma unroll
        for (int nt = 0; nt < 4; ++nt) {
            int r0 = wm * 32 + mt * 16 + g;
            int cc = wn * 32 + nt * 8 + tq * 2;
            Ysm[r0 * PY + cc]           = c[mt][nt][0];
            Ysm[r0 * PY + cc + 1]       = c[mt][nt][1];
            Ysm[(r0 + 8) * PY + cc]     = c[mt][nt][2];
            Ysm[(r0 + 8) * PY + cc + 1] = c[mt][nt][3];
        }
    __syncthreads();

    // ---- LIF over t + bitpack. 512 threads: token i = tid>>4, 8 channels
    // each (cg = tid&15); quads of lanes merged via shfl into 32-bit words.
    unsigned* dst = (nb == 0) ? g_qbits : ((nb == 1) ? g_kbits : g_vbits);
    {
        const int i = tid >> 4;
        const int cg = tid & 15;
        const int wj = cg >> 2;
        const int bitbase = (cg & 3) * 8;
        unsigned bits[4] = {0u, 0u, 0u, 0u};
#pragma unroll
        for (int j = 0; j < 2; ++j) {
            float4 y0 = *(const float4*)&Ysm[(0 * 32 + i) * PY + cg * 8 + j * 4];
            float4 y1 = *(const float4*)&Ysm[(1 * 32 + i) * PY + cg * 8 + j * 4];
            float4 y2 = *(const float4*)&Ysm[(2 * 32 + i) * PY + cg * 8 + j * 4];
            float4 y3 = *(const float4*)&Ysm[(3 * 32 + i) * PY + cg * 8 + j * 4];
            float ya[4][4] = {{y0.x, y0.y, y0.z, y0.w},
                              {y1.x, y1.y, y1.z, y1.w},
                              {y2.x, y2.y, y2.z, y2.w},
                              {y3.x, y3.y, y3.z, y3.w}};
#pragma unroll
            for (int cc = 0; cc < 4; ++cc) {
                float v = 0.f;
#pragma unroll
                for (int t = 0; t < 4; ++t) {
                    v += (ya[t][cc] - v) * 0.5f;   // v + (x - v)/tau, tau=2
                    if (v >= 1.0f) { bits[t] |= (1u << (bitbase + j * 4 + cc)); v = 0.f; }
                }
            }
        }
#pragma unroll
        for (int t = 0; t < 4; ++t) {
            bits[t] |= __shfl_xor_sync(0xffffffffu, bits[t], 1);
            bits[t] |= __shfl_xor_sync(0xffffffffu, bits[t], 2);
        }
        if ((cg & 3) == 0) {
#pragma unroll
            for (int t = 0; t < 4; ++t)
                dst[(t * TOK_TOTAL + tokbase + i) * 4 + wj] = bits[t];
        }
    }
}

// ------------------------------- Stage B -----------------------------------
// One block per (b', head): attn = SCALE*popc(q&k)+rpb -> d_out (float4,
// streaming stores); out1 = attn@v only if v has spikes (flag otherwise).
__global__ void __launch_bounds__(256) attn_kernel(
    const float* __restrict__ rpb_table, float* __restrict__ out)
{
    __shared__ unsigned qw[256], kw[256], vw[256];
    __shared__ float rpb_sm[1575];             // per-head slice, stride-1

    const int tid = threadIdx.x;
    const int bh = blockIdx.x;                 // = b'*4 + head
    const int bq = bh >> 2, head = bh & 3;

    qw[tid] = g_qbits[bh * 256 + tid];
    kw[tid] = g_kbits[bh * 256 + tid];
    vw[tid] = g_vbits[bh * 256 + tid];
    for (int idx = tid; idx < 1575; idx += 256)
        rpb_sm[idx] = rpb_table[idx * 4 + head];
    __syncthreads();

    // thread owns 4 consecutive m columns; 4 n-rows in flight per iteration
    const int u = tid & 63;                    // m-quad
    const int grp = tid >> 6;                  // n offset within group of 4
    unsigned km[4];
    int zm[4], ym[4], xm[4];
#pragma unroll
    for (int j = 0; j < 4; ++j) {
        int m = u * 4 + j;
        km[j] = kw[m];
        zm[j] = m >> 6; ym[j] = (m >> 3) & 7; xm[j] = m & 7;
    }
    float4* aout = (float4*)(out + 8388608 + (size_t)bh * 65536);
#pragma unroll 2
    for (int nb = 0; nb < 256; nb += 4) {
        int n = nb + grp;
        int zn = n >> 6, yn = (n >> 3) & 7, xn = n & 7;
        unsigned qn = qw[n];
        float4 r;
        {
            int ridx = (zn - zm[0] + 3) * 225 + (yn - ym[0] + 7) * 15 + (xn - xm[0] + 7);
            r.x = SCALE_F * (float)__popc(qn & km[0]) + rpb_sm[ridx];
        }
        {
            int ridx = (zn - zm[1] + 3) * 225 + (yn - ym[1] + 7) * 15 + (xn - xm[1] + 7);
            r.y = SCALE_F * (float)__popc(qn & km[1]) + rpb_sm[ridx];
        }
        {
            int ridx = (zn - zm[2] + 3) * 225 + (yn - ym[2] + 7) * 15 + (xn - xm[2] + 7);
            r.z = SCALE_F * (float)__popc(qn & km[2]) + rpb_sm[ridx];
        }
        {
            int ridx = (zn - zm[3] + 3) * 225 + (yn - ym[3] + 7) * 15 + (xn - xm[3] + 7);
            r.w = SCALE_F * (float)__popc(qn & km[3]) + rpb_sm[ridx];
        }
        __stcs(&aout[(size_t)n * 64 + u], r);
    }

    // out1 = attn @ v. Zero v tile -> flag only, no memory traffic.
    int vnz = __syncthreads_or(vw[tid] != 0u);
    if (tid == 0) g_vnz[bh] = vnz;
    if (vnz) {
        __shared__ int mlist[256];
        __shared__ int mcount;
        if (tid == 0) mcount = 0;
        __syncthreads();
        if (vw[tid] != 0u) { int p = atomicAdd(&mcount, 1); mlist[p] = tid; }
        __syncthreads();
        int cnt = mcount;
        for (int p = tid; p < 8192; p += 256) {
            int n = p >> 5, hd = p & 31;
            int zn = n >> 6, yn = (n >> 3) & 7, xn = n & 7;
            unsigned qn = qw[n];
            float acc = 0.f;
            for (int j = 0; j < cnt; ++j) {
                int m = mlist[j];
                if ((vw[m] >> hd) & 1u) {
                    int zk = m >> 6, yk = (m >> 3) & 7, xk = m & 7;
                    int ridx = (zn - zk + 3) * 225 + (yn - yk + 7) * 15 + (xn - xk + 7);
                    acc += SCALE_F * (float)__popc(qn & kw[m]) + rpb_sm[ridx];
                }
            }
            int row2 = (n >> 6) * TOK_TOTAL + bq * 64 + (n & 63);
            g_out1[(size_t)row2 * 128 + head * 32 + hd] = acc;
        }
    }
}

// ------------------------------- Stage C1 ----------------------------------
// Fast path: all 4 head flags of the b' are zero -> y == bproj exactly ->
// spikes depend only on (t, channel). 2048 blocks, 4 consecutive float4
// streaming stores per thread, fully coalesced.
__global__ void __launch_bounds__(256) proj_zero_kernel(
    const float* __restrict__ bproj, float* __restrict__ dout)
{
    const int tg = blockIdx.x * 256 + threadIdx.x;
    float4* o4 = (float4*)dout;
#pragma unroll
    for (int k = 0; k < 4; ++k) {
        int L = tg * 4 + k;                    // float4 id in out spike region
        int row = L >> 5, c4 = L & 31;         // row = t*16384 + token
        int t = row >> 14, token = row & 16383, bq = token >> 6;
        if (g_vnz[bq * 4 + 0] | g_vnz[bq * 4 + 1] |
            g_vnz[bq * 4 + 2] | g_vnz[bq * 4 + 3]) continue;
        float4 b4 = ((const float4*)bproj)[c4];
        float4 v = make_float4(0.f, 0.f, 0.f, 0.f);
        float4 s = make_float4(0.f, 0.f, 0.f, 0.f);
        for (int tt = 0; tt <= t; ++tt) {
            v.x += (b4.x - v.x) * 0.5f; v.y += (b4.y - v.y) * 0.5f;
            v.z += (b4.z - v.z) * 0.5f; v.w += (b4.w - v.w) * 0.5f;
            s.x = (v.x >= 1.f) ? 1.f : 0.f; if (v.x >= 1.f) v.x = 0.f;
            s.y = (v.y >= 1.f) ? 1.f : 0.f; if (v.y >= 1.f) v.y = 0.f;
            s.z = (v.z >= 1.f) ? 1.f : 0.f; if (v.z >= 1.f) v.z = 0.f;
            s.w = (v.w >= 1.f) ? 1.f : 0.f; if (v.w >= 1.f) v.w = 0.f;
        }
        __stcs(&o4[L], s);
    }
}

// ------------------------------- Stage C2 ----------------------------------
// Fallback: any head flag nonzero -> full out1 @ Wproj^T + bproj + LIF.
#define PX 132
__global__ void __launch_bounds__(256) proj_lif_kernel(
    const float* __restrict__ Wproj, const float* __restrict__ bproj,
    float* __restrict__ dout)
{
    extern __shared__ float sm[];
    float* X2s = sm;                 // 128 x PX
    float* Wsm = sm + 128 * PX;      // 128 x 128, stored transposed [k][d]
    __shared__ int hflag[4];

    const int tid = threadIdx.x;
    const int tokbase = blockIdx.x * 32;
    const int bq = tokbase >> 6;     // 32 tokens always inside one b'

    if (tid < 4) hflag[tid] = g_vnz[bq * 4 + tid];
    __syncthreads();
    if (!(hflag[0] | hflag[1] | hflag[2] | hflag[3])) return;  // C1 handles

    {
        const int lane = tid & 31, rg = tid >> 5;
        const int hfl = hflag[lane >> 3];      // float4 spans one head's chans
        for (int it = 0; it < 16; ++it) {
            int m = it * 8 + rg;
            int t = m >> 5, i = m & 31;
            float4 v4 = hfl
                ? *(const float4*)(g_out1 + (size_t)(t * TOK_TOTAL + tokbase + i) * 128 + lane * 4)
                : make_float4(0.f, 0.f, 0.f, 0.f);
            X2s[m * PX + lane * 4 + 0] = v4.x;
            X2s[m * PX + lane * 4 + 1] = v4.y;
            X2s[m * PX + lane * 4 + 2] = v4.z;
            X2s[m * PX + lane * 4 + 3] = v4.w;
        }
    }
    for (int idx = tid; idx < 16384; idx += 256) {
        int d = idx >> 7, k = idx & 127;
        Wsm[k * 128 + d] = Wproj[idx];         // transpose: conflict-free reads
    }
    __syncthreads();
    const int d = tid & 127, i0 = tid >> 7;
    float bj = bproj[d];
    for (int jj = 0; jj < 16; ++jj) {
        int i = i0 * 16 + jj;
        float a0 = 0.f, a1 = 0.f, a2 = 0.f, a3 = 0.f;
        for (int k = 0; k < 128; ++k) {
            float wv = Wsm[k * 128 + d];
            a0 += X2s[(0 * 32 + i) * PX + k] * wv;
            a1 += X2s[(1 * 32 + i) * PX + k] * wv;
            a2 += X2s[(2 * 32 + i) * PX + k] * wv;
            a3 += X2s[(3 * 32 + i) * PX + k] * wv;
        }
        float ys[4] = {a0 + bj, a1 + bj, a2 + bj, a3 + bj};
        float v = 0.f;
#pragma unroll
        for (int t = 0; t < 4; ++t) {
            v += (ys[t] - v) * 0.5f;
            float s = (v >= 1.f) ? 1.f : 0.f;
            if (v >= 1.f) v = 0.f;
            dout[(size_t)(t * TOK_TOTAL + tokbase + i) * 128 + d] = s;
        }
    }
}

// ---------------------------------------------------------------------------
extern "C" void kernel_launch(void* const* d_in, const int* in_sizes, int n_in,
                              void* d_out, int out_size) {
    const float* x   = (const float*)d_in[0];
    const float* Wq  = (const float*)d_in[1];
    const float* Wk  = (const float*)d_in[2];
    const float* Wv  = (const float*)d_in[3];
    const float* rpb = (const float*)d_in[4];
    const float* Wp  = (const float*)d_in[5];
    const float* bp  = (const float*)d_in[6];
    float* out = (float*)d_out;

    const int gemm_smem = 2 * 128 * PA * 2;            // 69632 B -> 2 CTAs/SM
    const int proj_smem = (128 * PX + 16384) * 4;      // 133120 B
    cudaFuncSetAttribute(gemm_qkv_lif_kernel,
                         cudaFuncAttributeMaxDynamicSharedMemorySize, gemm_smem);
    cudaFuncSetAttribute(proj_lif_kernel,
                         cudaFuncAttributeMaxDynamicSharedMemorySize, proj_smem);

    gemm_qkv_lif_kernel<<<dim3(512, 3), 512, gemm_smem>>>(x, Wq, Wk, Wv);
    attn_kernel<<<1024, 256>>>(rpb, out);
    proj_zero_kernel<<<2048, 256>>>(bp, out);
    proj_lif_kernel<<<512, 256, proj_smem>>>(Wp, bp, out);
}

// round 10
// speedup vs baseline: 1.2658x; 1.0181x over previous
#include <cuda_runtime.h>
#include <cuda_bf16.h>
#include <cstdint>

// ---------------------------------------------------------------------------
// Spiking Swin block:
//   q,k,v = lif(x @ W^T)  -> binary, bitpacked (literal reshape == flat bitpack)
//   attn  = SCALE*popc(q&k) + rpb          (written to d_out[8388608..])
//   out1  = attn @ v  (v binary; zero v-tile -> flag, no traffic)
//   out   = lif(out1 @ Wproj^T + bproj)    (written to d_out[0..8388608))
//
// Spike words use a fixed intra-byte bit permutation (shared by q/k/v):
//   word bit p  <->  channel (p & ~7) | ((p&3)<<1) | ((p>>2)&1)
// popc(q&k) is invariant; fallback paths decode explicitly.
// ---------------------------------------------------------------------------

#define TOK_TOTAL 16384          // B_*H*W = 256*64
#define SCALE_F   0.17677669529663687f

__device__ unsigned g_qbits[262144];
__device__ unsigned g_kbits[262144];
__device__ unsigned g_vbits[262144];
__device__ int      g_vnz[1024];       // per (b',head): v tile has any spike
__device__ float    g_out1[8388608];   // proj input; only written where flag!=0

#define PA 136   // bf16 pitch (272B rows: ldmatrix conflict-free)

__device__ __forceinline__ void ldsm4(uint32_t addr, unsigned& r0, unsigned& r1,
                                      unsigned& r2, unsigned& r3) {
    asm volatile("ldmatrix.sync.aligned.m8n8.x4.shared.b16 {%0,%1,%2,%3}, [%4];"
                 : "=r"(r0), "=r"(r1), "=r"(r2), "=r"(r3) : "r"(addr));
}

__device__ __forceinline__ void mma16816(float* c, unsigned a0, unsigned a1,
                                         unsigned a2, unsigned a3,
                                         unsigned b0, unsigned b1) {
    asm volatile(
        "mma.sync.aligned.m16n8k16.row.col.f32.bf16.bf16.f32 "
        "{%0,%1,%2,%3}, {%4,%5,%6,%7}, {%8,%9}, {%0,%1,%2,%3};"
        : "+f"(c[0]), "+f"(c[1]), "+f"(c[2]), "+f"(c[3])
        : "r"(a0), "r"(a1), "r"(a2), "r"(a3), "r"(b0), "r"(b1));
}

// ------------------------------- Stage A -----------------------------------
// C(128x128) = X_tile @ W^T in bf16 (spike bits exact: LIF margin >> bf16 err).
// A rows token-interleaved (row m <-> token m>>2, t=m&3) so each warp's tile
// holds all 4 timesteps of its tokens -> LIF in registers via shfl transpose,
// spike words via ballot. No epilogue smem, one __syncthreads total.
__global__ void __launch_bounds__(512, 2) gemm_qkv_lif_kernel(
    const float* __restrict__ x,
    const float* __restrict__ Wq,
    const float* __restrict__ Wk,
    const float* __restrict__ Wv)
{
    extern __shared__ char smem_raw[];
    __nv_bfloat16* Ah = (__nv_bfloat16*)smem_raw;      // 34816 B
    __nv_bfloat16* Bh = Ah + 128 * PA;                 // 34816 B

    const int tid = threadIdx.x;
    const int nb = blockIdx.y;                 // 0:q 1:k 2:v
    const int tokbase = blockIdx.x * 32;
    const float* W = (nb == 0) ? Wq : ((nb == 1) ? Wk : Wv);

    // ---- load. A row m <- x[t = m&3][token tokbase + (m>>2)]; B row m <- W[m]
#pragma unroll
    for (int it = 0; it < 8; ++it) {
        int idx = it * 512 + tid;              // float4 id, 4096 total
        int m = idx >> 5, c4 = idx & 31;
        int i = m >> 2, t = m & 3;
        float4 v4 = *(const float4*)(x + (size_t)(t * TOK_TOTAL + tokbase + i) * 128 + c4 * 4);
        __nv_bfloat162* d = (__nv_bfloat162*)(Ah + m * PA + c4 * 4);
        d[0] = __floats2bfloat162_rn(v4.x, v4.y);
        d[1] = __floats2bfloat162_rn(v4.z, v4.w);
        float4 w4 = *(const float4*)(W + (size_t)m * 128 + c4 * 4);
        __nv_bfloat162* dw = (__nv_bfloat162*)(Bh + m * PA + c4 * 4);
        dw[0] = __floats2bfloat162_rn(w4.x, w4.y);
        dw[1] = __floats2bfloat162_rn(w4.z, w4.w);
    }
    __syncthreads();

    const int w = tid >> 5, lane = tid & 31;
    const int wm = w & 3, wn = w >> 2;         // warp tile: 32 rows x 32 cols
    const int r8 = lane & 7;
    const int lb3 = (lane >> 3) & 1, lb4 = (lane >> 4) & 1;

    // ldmatrix x4 lane addresses (bytes, shared space)
    const uint32_t Abase = (uint32_t)__cvta_generic_to_shared(Ah);
    const uint32_t Bbase = (uint32_t)__cvta_generic_to_shared(Bh);
    // A: matrix m: row-half = m&1 (lb3), k-half = m>>1 (lb4)
    const uint32_t aaddr0 = Abase + (uint32_t)(((wm * 32 + lb3 * 8 + r8) * PA + lb4 * 8) * 2);
    const uint32_t aaddr1 = aaddr0 + 16 * PA * 2;
    // B: matrix m: k-half = m&1 (lb3), n-half = m>>1 (lb4)
    const uint32_t baddr0 = Bbase + (uint32_t)(((wn * 32 + lb4 * 8 + r8) * PA + lb3 * 8) * 2);
    const uint32_t baddr1 = baddr0 + 16 * PA * 2;

    float c[2][4][4];
#pragma unroll
    for (int mt = 0; mt < 2; ++mt)
#pragma unroll
        for (int nt = 0; nt < 4; ++nt)
#pragma unroll
            for (int r = 0; r < 4; ++r) c[mt][nt][r] = 0.f;

#pragma unroll
    for (int kk = 0; kk < 8; ++kk) {
        unsigned b0, b1, b2, b3, b4, b5, b6, b7;
        ldsm4(baddr0 + kk * 32, b0, b1, b2, b3);   // nt 0,1
        ldsm4(baddr1 + kk * 32, b4, b5, b6, b7);   // nt 2,3
        unsigned a0, a1, a2, a3;
        ldsm4(aaddr0 + kk * 32, a0, a1, a2, a3);   // mt 0
        mma16816(c[0][0], a0, a1, a2, a3, b0, b1);
        mma16816(c[0][1], a0, a1, a2, a3, b2, b3);
        mma16816(c[0][2], a0, a1, a2, a3, b4, b5);
        mma16816(c[0][3], a0, a1, a2, a3, b6, b7);
        ldsm4(aaddr1 + kk * 32, a0, a1, a2, a3);   // mt 1
        mma16816(c[1][0], a0, a1, a2, a3, b0, b1);
        mma16816(c[1][1], a0, a1, a2, a3, b2, b3);
        mma16816(c[1][2], a0, a1, a2, a3, b4, b5);
        mma16816(c[1][3], a0, a1, a2, a3, b6, b7);
    }

    // ---- register epilogue. Per (mt,nt): thread holds V[j]=c[..][j] with
    // j = 2*delta + cbit: (token Tb+2delta, chan cc+cbit) at t = k = (lane>>2)&3.
    // 4x4 shfl-butterfly transpose over lanes {l^4, l^8} puts each lane's own
    // (token,chan) t-series into V[0..3]; LIF -> 4 spike bits.
    const bool k0 = (lane & 4) != 0;
    const bool k1 = (lane & 8) != 0;
    unsigned sbp = 0;
#pragma unroll
    for (int mt = 0; mt < 2; ++mt)
#pragma unroll
        for (int nt = 0; nt < 4; ++nt) {
            float V0 = c[mt][nt][0], V1 = c[mt][nt][1];
            float V2 = c[mt][nt][2], V3 = c[mt][nt][3];
            // step 1 (mask 4): swap slot-bit0 with lane k-bit0
            float e0 = k0 ? V0 : V1;
            float e1 = k0 ? V2 : V3;
            float r0 = __shfl_xor_sync(0xffffffffu, e0, 4);
            float r1 = __shfl_xor_sync(0xffffffffu, e1, 4);
            V0 = k0 ? r0 : V0;  V1 = k0 ? V1 : r0;
            V2 = k0 ? r1 : V2;  V3 = k0 ? V3 : r1;
            // step 2 (mask 8): swap slot-bit1 with lane k-bit1
            float f0 = k1 ? V0 : V2;
            float f1 = k1 ? V1 : V3;
            float s0 = __shfl_xor_sync(0xffffffffu, f0, 8);
            float s1 = __shfl_xor_sync(0xffffffffu, f1, 8);
            V0 = k1 ? s0 : V0;  V2 = k1 ? V2 : s0;
            V1 = k1 ? s1 : V1;  V3 = k1 ? V3 : s1;
            // V[t] = y at t=0..3 for this lane's (token, channel); LIF:
            unsigned sb = 0;
            float v = V0 * 0.5f;
            if (v >= 1.0f) { sb |= 1u; v = 0.f; }
            v += (V1 - v) * 0.5f;
            if (v >= 1.0f) { sb |= 2u; v = 0.f; }
            v += (V2 - v) * 0.5f;
            if (v >= 1.0f) { sb |= 4u; v = 0.f; }
            v += (V3 - v) * 0.5f;
            if (v >= 1.0f) { sb |= 8u; }
            sbp |= sb << ((mt * 4 + nt) * 4);
        }

    // ---- word assembly via ballot. Writer lane l -> (t=l&3, token tau=l>>2).
    const int t_w  = lane & 3;
    const int tau  = lane >> 2;                // 0..7 within wm's 8 tokens
    const int mt_w = (lane >> 4) & 1;
    const int rem  = (lane >> 2) & 3;
    const int byteidx = ((rem & 1) << 1) | (rem >> 1);
    unsigned word = 0;
#pragma unroll
    for (int nt = 0; nt < 4; ++nt) {
        unsigned q00 = __ballot_sync(0xffffffffu, (sbp >> ((0 * 4 + nt) * 4 + 0)) & 1u);
        unsigned q01 = __ballot_sync(0xffffffffu, (sbp >> ((0 * 4 + nt) * 4 + 1)) & 1u);
        unsigned q02 = __ballot_sync(0xffffffffu, (sbp >> ((0 * 4 + nt) * 4 + 2)) & 1u);
        unsigned q03 = __ballot_sync(0xffffffffu, (sbp >> ((0 * 4 + nt) * 4 + 3)) & 1u);
        unsigned q10 = __ballot_sync(0xffffffffu, (sbp >> ((1 * 4 + nt) * 4 + 0)) & 1u);
        unsigned q11 = __ballot_sync(0xffffffffu, (sbp >> ((1 * 4 + nt) * 4 + 1)) & 1u);
        unsigned q12 = __ballot_sync(0xffffffffu, (sbp >> ((1 * 4 + nt) * 4 + 2)) & 1u);
        unsigned q13 = __ballot_sync(0xffffffffu, (sbp >> ((1 * 4 + nt) * 4 + 3)) & 1u);
        unsigned bm0 = mt_w ? q10 : q00;
        unsigned bm1 = mt_w ? q11 : q01;
        unsigned bm2 = mt_w ? q12 : q02;
        unsigned bm3 = mt_w ? q13 : q03;
        unsigned s01 = (t_w & 1) ? bm1 : bm0;
        unsigned s23 = (t_w & 1) ? bm3 : bm2;
        unsigned sel = (t_w & 2) ? s23 : s01;
        word |= ((sel >> (byteidx * 8)) & 0xffu) << (nt * 8);
    }
    unsigned* dst = (nb == 0) ? g_qbits : ((nb == 1) ? g_kbits : g_vbits);
    dst[(t_w * TOK_TOTAL + tokbase + wm * 8 + tau) * 4 + wn] = word;
}

// ------------------------------- Stage B -----------------------------------
// One block per (b', head): attn = SCALE*popc(q&k)+rpb -> d_out (float4,
// streaming stores); out1 = attn@v only if v has spikes (flag otherwise).
__global__ void __launch_bounds__(256) attn_kernel(
    const float* __restrict__ rpb_table, float* __restrict__ out)
{
    __shared__ unsigned qw[256], kw[256], vw[256];
    __shared__ float rpb_sm[1575];             // per-head slice, stride-1

    const int tid = threadIdx.x;
    const int bh = blockIdx.x;                 // = b'*4 + head
    const int bq = bh >> 2, head = bh & 3;

    qw[tid] = g_qbits[bh * 256 + tid];
    kw[tid] = g_kbits[bh * 256 + tid];
    vw[tid] = g_vbits[bh * 256 + tid];
    for (int idx = tid; idx < 1575; idx += 256)
        rpb_sm[idx] = rpb_table[idx * 4 + head];
    __syncthreads();

    const int u = tid & 63;                    // m-quad
    const int grp = tid >> 6;                  // n offset within group of 4
    unsigned km[4];
    int zm[4], ym[4], xm[4];
#pragma unroll
    for (int j = 0; j < 4; ++j) {
        int m = u * 4 + j;
        km[j] = kw[m];
        zm[j] = m >> 6; ym[j] = (m >> 3) & 7; xm[j] = m & 7;
    }
    float4* aout = (float4*)(out + 8388608 + (size_t)bh * 65536);
#pragma unroll 2
    for (int nb = 0; nb < 256; nb += 4) {
        int n = nb + grp;
        int zn = n >> 6, yn = (n >> 3) & 7, xn = n & 7;
        unsigned qn = qw[n];
        float4 r;
        {
            int ridx = (zn - zm[0] + 3) * 225 + (yn - ym[0] + 7) * 15 + (xn - xm[0] + 7);
            r.x = SCALE_F * (float)__popc(qn & km[0]) + rpb_sm[ridx];
        }
        {
            int ridx = (zn - zm[1] + 3) * 225 + (yn - ym[1] + 7) * 15 + (xn - xm[1] + 7);
            r.y = SCALE_F * (float)__popc(qn & km[1]) + rpb_sm[ridx];
        }
        {
            int ridx = (zn - zm[2] + 3) * 225 + (yn - ym[2] + 7) * 15 + (xn - xm[2] + 7);
            r.z = SCALE_F * (float)__popc(qn & km[2]) + rpb_sm[ridx];
        }
        {
            int ridx = (zn - zm[3] + 3) * 225 + (yn - ym[3] + 7) * 15 + (xn - xm[3] + 7);
            r.w = SCALE_F * (float)__popc(qn & km[3]) + rpb_sm[ridx];
        }
        __stcs(&aout[(size_t)n * 64 + u], r);
    }

    // out1 = attn @ v. Zero v tile -> flag only, no memory traffic.
    int vnz = __syncthreads_or(vw[tid] != 0u);
    if (tid == 0) g_vnz[bh] = vnz;
    if (vnz) {
        __shared__ int mlist[256];
        __shared__ int mcount;
        if (tid == 0) mcount = 0;
        __syncthreads();
        if (vw[tid] != 0u) { int p = atomicAdd(&mcount, 1); mlist[p] = tid; }
        __syncthreads();
        int cnt = mcount;
        for (int p = tid; p < 8192; p += 256) {
            int n = p >> 5, hd = p & 31;       // hd = permuted bit position
            int zn = n >> 6, yn = (n >> 3) & 7, xn = n & 7;
            unsigned qn = qw[n];
            float acc = 0.f;
            for (int j = 0; j < cnt; ++j) {
                int m = mlist[j];
                if ((vw[m] >> hd) & 1u) {
                    int zk = m >> 6, yk = (m >> 3) & 7, xk = m & 7;
                    int ridx = (zn - zk + 3) * 225 + (yn - yk + 7) * 15 + (xn - xk + 7);
                    acc += SCALE_F * (float)__popc(qn & kw[m]) + rpb_sm[ridx];
                }
            }
            // decode permuted bit position -> real channel offset
            int co = (hd & ~7) | ((hd & 3) << 1) | ((hd >> 2) & 1);
            int row2 = (n >> 6) * TOK_TOTAL + bq * 64 + (n & 63);
            g_out1[(size_t)row2 * 128 + head * 32 + co] = acc;
        }
    }
}

// ------------------------------- Stage C1 ----------------------------------
// Fast path: all 4 head flags of the b' are zero -> y == bproj exactly ->
// spikes depend only on (t, channel). Coalesced float4 streaming stores.
__global__ void __launch_bounds__(256) proj_zero_kernel(
    const float* __restrict__ bproj, float* __restrict__ dout)
{
    const int tg = blockIdx.x * 256 + threadIdx.x;
    float4* o4 = (float4*)dout;
#pragma unroll
    for (int k = 0; k < 4; ++k) {
        int L = tg * 4 + k;                    // float4 id in out spike region
        int row = L >> 5, c4 = L & 31;         // row = t*16384 + token
        int t = row >> 14, token = row & 16383, bq = token >> 6;
        if (g_vnz[bq * 4 + 0] | g_vnz[bq * 4 + 1] |
            g_vnz[bq * 4 + 2] | g_vnz[bq * 4 + 3]) continue;
        float4 b4 = ((const float4*)bproj)[c4];
        float4 v = make_float4(0.f, 0.f, 0.f, 0.f);
        float4 s = make_float4(0.f, 0.f, 0.f, 0.f);
        for (int tt = 0; tt <= t; ++tt) {
            v.x += (b4.x - v.x) * 0.5f; v.y += (b4.y - v.y) * 0.5f;
            v.z += (b4.z - v.z) * 0.5f; v.w += (b4.w - v.w) * 0.5f;
            s.x = (v.x >= 1.f) ? 1.f : 0.f; if (v.x >= 1.f) v.x = 0.f;
            s.y = (v.y >= 1.f) ? 1.f : 0.f; if (v.y >= 1.f) v.y = 0.f;
            s.z = (v.z >= 1.f) ? 1.f : 0.f; if (v.z >= 1.f) v.z = 0.f;
            s.w = (v.w >= 1.f) ? 1.f : 0.f; if (v.w >= 1.f) v.w = 0.f;
        }
        __stcs(&o4[L], s);
    }
}

// ------------------------------- Stage C2 ----------------------------------
// Fallback (runs ~never): any head flag nonzero -> out1 @ Wproj^T + bproj +
// LIF, straight from global memory. No smem request -> cheap early return.
__global__ void __launch_bounds__(256) proj_lif_kernel(
    const float* __restrict__ Wproj, const float* __restrict__ bproj,
    float* __restrict__ dout)
{
    __shared__ int hflag[4];
    const int tid = threadIdx.x;
    const int tokbase = blockIdx.x * 32;
    const int bq = tokbase >> 6;

    if (tid < 4) hflag[tid] = g_vnz[bq * 4 + tid];
    __syncthreads();
    if (!(hflag[0] | hflag[1] | hflag[2] | hflag[3])) return;  // C1 handled

    const int d = tid & 127, half = tid >> 7;
    float bj = bproj[d];
    for (int jj = 0; jj < 16; ++jj) {
        int i = half * 16 + jj;
        float a0 = 0.f, a1 = 0.f, a2 = 0.f, a3 = 0.f;
        for (int h = 0; h < 4; ++h) {
            if (!hflag[h]) continue;           // unwritten g_out1 == exact 0
            for (int k = 0; k < 32; ++k) {
                int ch = h * 32 + k;
                float wv = Wproj[d * 128 + ch];
                a0 += g_out1[(size_t)(0 * TOK_TOTAL + tokbase + i) * 128 + ch] * wv;
                a1 += g_out1[(size_t)(1 * TOK_TOTAL + tokbase + i) * 128 + ch] * wv;
                a2 += g_out1[(size_t)(2 * TOK_TOTAL + tokbase + i) * 128 + ch] * wv;
                a3 += g_out1[(size_t)(3 * TOK_TOTAL + tokbase + i) * 128 + ch] * wv;
            }
        }
        float ys[4] = {a0 + bj, a1 + bj, a2 + bj, a3 + bj};
        float v = 0.f;
#pragma unroll
        for (int t = 0; t < 4; ++t) {
            v += (ys[t] - v) * 0.5f;
            float s = (v >= 1.f) ? 1.f : 0.f;
            if (v >= 1.f) v = 0.f;
            dout[(size_t)(t * TOK_TOTAL + tokbase + i) * 128 + d] = s;
        }
    }
}

// ---------------------------------------------------------------------------
extern "C" void kernel_launch(void* const* d_in, const int* in_sizes, int n_in,
                              void* d_out, int out_size) {
    const float* x   = (const float*)d_in[0];
    const float* Wq  = (const float*)d_in[1];
    const float* Wk  = (const float*)d_in[2];
    const float* Wv  = (const float*)d_in[3];
    const float* rpb = (const float*)d_in[4];
    const float* Wp  = (const float*)d_in[5];
    const float* bp  = (const float*)d_in[6];
    float* out = (float*)d_out;

    const int gemm_smem = 2 * 128 * PA * 2;            // 69632 B -> 2 CTAs/SM
    cudaFuncSetAttribute(gemm_qkv_lif_kernel,
                         cudaFuncAttributeMaxDynamicSharedMemorySize, gemm_smem);

    gemm_qkv_lif_kernel<<<dim3(512, 3), 512, gemm_smem>>>(x, Wq, Wk, Wv);
    attn_kernel<<<1024, 256>>>(rpb, out);
    proj_zero_kernel<<<2048, 256>>>(bp, out);
    proj_lif_kernel<<<512, 256>>>(Wp, bp, out);
}